// round 13
// baseline (speedup 1.0000x reference)
#include <cuda_runtime.h>
#include <cuda_bf16.h>
#include <mma.h>
#include <cstdint>

using namespace nvcuda;

// ---------------------------------------------------------------------------
// Problem constants (fixed by setup_inputs)
// ---------------------------------------------------------------------------
#define BB     64
#define NTOT   4096
#define XD     256
#define HDIM   256
#define GDIM   512
#define HID    512
#define KC     32
#define NTOK   2048
#define NH     (NTOK + 1)      // h tokens 0..2048 (2049)
#define NQ     (NTOT - NH)     // q tokens 2049..4095 (2047)
#define ROWS_HK (BB * (KC + 1))
#define ROWS_H  (BB * (2*KC + 1))
#define ROWS_E  (BB * (KC + 1))
#define QCHUNK 8

// ---------------------------------------------------------------------------
// Scratch
// ---------------------------------------------------------------------------
constexpr long long OFF_Y   = 0;
constexpr long long OFF_RH  = OFF_Y   + (long long)BB*NTOT*HID;
constexpr long long OFF_RQP = OFF_RH  + (long long)BB*(KC+1)*HID;
constexpr long long OFF_RQ  = OFF_RQP + (long long)QCHUNK*BB*HID;
constexpr long long OFF_HK  = OFF_RQ  + (long long)BB*HID;
constexpr long long OFF_H   = OFF_HK  + (long long)BB*(KC+1)*HDIM;
constexpr long long OFF_G1  = OFF_H   + (long long)BB*(2*KC+1)*HDIM;
constexpr long long OFF_GS  = OFF_G1  + (long long)ROWS_H*HID;
constexpr long long OFF_S   = OFF_GS  + (long long)ROWS_H*GDIM;
constexpr long long OFF_Q   = OFF_S   + (long long)BB*GDIM;
constexpr long long OFF_UU  = OFF_Q   + (long long)BB*HDIM;
constexpr long long OFF_EH  = OFF_UU  + (long long)ROWS_E*(GDIM+HDIM);
constexpr long long OFF_RS  = OFF_EH  + (long long)ROWS_E*HID;
constexpr long long SCRATCH_TOTAL = OFF_RS + ROWS_HK;

__device__ float g_buf[SCRATCH_TOTAL];
__device__ int   g_order[NTOK];
__device__ int   g_starts[KC];
__device__ int   g_counts[KC];
__device__ float g_countsf[KC];
// transposed fp32 weights: [0]=h [1]=q, each [512][256]
__device__ float g_wtf[2][HID * XD];

// ---------------------------------------------------------------------------
// cp.async helpers
// ---------------------------------------------------------------------------
__device__ __forceinline__ uint32_t smem_u32(const void* p) {
    uint32_t a;
    asm("{ .reg .u64 t; cvta.to.shared.u64 t, %1; cvt.u32.u64 %0, t; }" : "=r"(a) : "l"(p));
    return a;
}
__device__ __forceinline__ void cp16(uint32_t dst, const void* src) {
    asm volatile("cp.async.cg.shared.global [%0], [%1], 16;" :: "r"(dst), "l"(src));
}
#define CP_COMMIT() asm volatile("cp.async.commit_group;" ::: "memory")
#define CP_WAIT1()  asm volatile("cp.async.wait_group 1;" ::: "memory")
#define CP_WAIT0()  asm volatile("cp.async.wait_group 0;" ::: "memory")

// ---------------------------------------------------------------------------
// Weight prep: W[256][512] fp32 -> WT fp32 [512][256]
// ---------------------------------------------------------------------------
__global__ void prep_weights_kernel(const float* __restrict__ Wh1, const float* __restrict__ Wq1) {
    int i = blockIdx.x * blockDim.x + threadIdx.x;
    if (i >= XD * HID) return;
    int k = i / HID, n = i % HID;
    g_wtf[0][n * XD + k] = Wh1[i];
    g_wtf[1][n * XD + k] = Wq1[i];
}

// ---------------------------------------------------------------------------
// Layer-1 wmma TF32 GEMM, cp.async double-buffered.
// Y[token] = relu(data[token] @ W1 + b1), single-pass tf32 (m16n16k8).
// grid (4 nblk, 33 tile, 64 batch), 512 threads (16 warps, warp tile 32x32).
// CTA tile M=128 x N=128, K=256 in 8 chunks of 32 floats.
// ---------------------------------------------------------------------------
#define KCH    32
#define LDAF   40                       // padded f32 row stride (32 + 8)
#define TILE_F (128 * LDAF)             // 5120 floats per tile
#define BUF_B  (2 * TILE_F * 4)         // bytes per buffer (A,B) = 40960
#define LDS_F  132                      // padded f32 staging stride (128 + 4)
#define L1_SMEM (2 * BUF_B)             // 81920 B (stage 128*132*4=67584 fits)

__global__ void __launch_bounds__(512) layer1_wmma_kernel(
    const float* __restrict__ data,
    const float* __restrict__ bh, const float* __restrict__ bq)
{
    extern __shared__ char smem[];
    const uint32_t sb = smem_u32(smem);
    float* stage = (float*)smem;

    const int tid = threadIdx.x;
    const int wid = tid >> 5;
    const int wm = wid >> 2;          // 0..3 (M direction, 32 rows each)
    const int wn = wid & 3;           // 0..3 (N direction, 32 cols each)

    const int nb = blockIdx.x, tile = blockIdx.y, b = blockIdx.z;
    const bool is_h = tile < 17;
    const int tile_start = is_h ? tile * 128 : NH + (tile - 17) * 128;
    const int token_lim = is_h ? NTOK : (NTOT - 1);     // inclusive
    const int n0 = nb * 128;
    const float* WT = is_h ? g_wtf[0] : g_wtf[1];
    const float* bias = is_h ? bh : bq;

    // per-thread load coordinates: row 0..127, seg (tid&3)*8 floats (2x 16B)
    const int r = tid >> 2;
    const int seg = (tid & 3) * 8;
    int token_ld = tile_start + r;
    if (token_ld > NTOT - 1) token_ld = NTOT - 1;
    const float* arow = data + ((long long)b * NTOT + token_ld) * XD;
    const float* wrow = WT + (long long)(n0 + r) * XD;
    const uint32_t soff = (uint32_t)(r * LDAF + seg) * 4;

    wmma::fragment<wmma::accumulator, 16, 16, 8, float> acc[2][2];
#pragma unroll
    for (int i = 0; i < 2; i++)
#pragma unroll
        for (int j = 0; j < 2; j++) wmma::fill_fragment(acc[i][j], 0.0f);

    // ---- pipeline: issue chunk 0
    {
        const uint32_t d = sb + soff;
        cp16(d,                 arow + seg);
        cp16(d + 16,            arow + seg + 4);
        cp16(d + TILE_F * 4,      wrow + seg);
        cp16(d + TILE_F * 4 + 16, wrow + seg + 4);
        CP_COMMIT();
    }

    for (int ch = 0; ch < 8; ch++) {
        if (ch < 7) {
            const int k0 = (ch + 1) * KCH;
            const uint32_t d = sb + ((ch + 1) & 1) * BUF_B + soff;
            cp16(d,                 arow + k0 + seg);
            cp16(d + 16,            arow + k0 + seg + 4);
            cp16(d + TILE_F * 4,      wrow + k0 + seg);
            cp16(d + TILE_F * 4 + 16, wrow + k0 + seg + 4);
            CP_COMMIT();
            CP_WAIT1();
        } else {
            CP_WAIT0();
        }
        __syncthreads();

        const float* buf = (const float*)(smem + (ch & 1) * BUF_B);
        const float* sA = buf;
        const float* sB = buf + TILE_F;

#pragma unroll
        for (int ks = 0; ks < 4; ks++) {
            const int ko = ks * 8;
            wmma::fragment<wmma::matrix_a, 16, 16, 8, wmma::precision::tf32, wmma::row_major> a[2];
            wmma::fragment<wmma::matrix_b, 16, 16, 8, wmma::precision::tf32, wmma::col_major> bf[2];
#pragma unroll
            for (int i = 0; i < 2; i++) {
                wmma::load_matrix_sync(a[i], &sA[(wm * 32 + i * 16) * LDAF + ko], LDAF);
#pragma unroll
                for (int t = 0; t < a[i].num_elements; t++)
                    a[i].x[t] = wmma::__float_to_tf32(a[i].x[t]);
            }
#pragma unroll
            for (int j = 0; j < 2; j++) {
                wmma::load_matrix_sync(bf[j], &sB[(wn * 32 + j * 16) * LDAF + ko], LDAF);
#pragma unroll
                for (int t = 0; t < bf[j].num_elements; t++)
                    bf[j].x[t] = wmma::__float_to_tf32(bf[j].x[t]);
            }
#pragma unroll
            for (int i = 0; i < 2; i++)
#pragma unroll
                for (int j = 0; j < 2; j++)
                    wmma::mma_sync(acc[i][j], a[i], bf[j], acc[i][j]);
        }
        __syncthreads();
    }

    // ---- epilogue: stage accumulators, add bias + relu, write Y
#pragma unroll
    for (int i = 0; i < 2; i++)
#pragma unroll
        for (int j = 0; j < 2; j++)
            wmma::store_matrix_sync(&stage[(wm * 32 + i * 16) * LDS_F + wn * 32 + j * 16],
                                    acc[i][j], LDS_F, wmma::mem_row_major);
    __syncthreads();

    const int token = tile_start + r;
    if (token <= token_lim) {
        const int c0 = (tid & 3) * 32;
        float* yrow = g_buf + OFF_Y + ((long long)b * NTOT + token) * HID + n0;
#pragma unroll
        for (int u = 0; u < 8; u++) {
            int c = c0 + u * 4;
            float4 v = *(float4*)&stage[r * LDS_F + c];
            float4 o;
            o.x = fmaxf(v.x + bias[n0 + c + 0], 0.f);
            o.y = fmaxf(v.y + bias[n0 + c + 1], 0.f);
            o.z = fmaxf(v.z + bias[n0 + c + 2], 0.f);
            o.w = fmaxf(v.w + bias[n0 + c + 3], 0.f);
            *(float4*)(yrow + c) = o;
        }
    }
}

// ---------------------------------------------------------------------------
// Counting sort of cs0 (deterministic)
// ---------------------------------------------------------------------------
__global__ void build_order_kernel(const int* __restrict__ cs) {
    __shared__ int s_cnt[KC];
    int tid = threadIdx.x, lane = tid & 31, w = tid >> 5;
    if (tid < KC) s_cnt[tid] = 0;
    __syncthreads();
    for (int i = tid; i < NTOK; i += blockDim.x) atomicAdd(&s_cnt[cs[i]], 1);
    __syncthreads();
    if (tid == 0) {
        int run = 0;
        for (int k = 0; k < KC; k++) {
            g_starts[k] = run; g_counts[k] = s_cnt[k];
            g_countsf[k] = (float)s_cnt[k]; run += s_cnt[k];
        }
    }
    __syncthreads();
    if (w < KC) {
        int base = g_starts[w];
        for (int i0 = 0; i0 < NTOK; i0 += 32) {
            int t = i0 + lane;
            int c = cs[t];
            unsigned m = __ballot_sync(0xffffffffu, c == w);
            if (c == w) g_order[base + __popc(m & ((1u << lane) - 1))] = t;
            base += __popc(m);
        }
    }
}

__global__ void build_rowscale_kernel() {
    int i = blockIdx.x * blockDim.x + threadIdx.x;
    if (i < ROWS_HK) {
        int k = i % (KC + 1);
        g_buf[OFF_RS + i] = (k < KC) ? g_countsf[k] : 1.0f;
    }
}

// ---------------------------------------------------------------------------
// SIMT SGEMM for small layers
// ---------------------------------------------------------------------------
#define GBM 128
#define GBN 64
#define GBK 16
__global__ void __launch_bounds__(256) sgemm_kernel(
    const float* __restrict__ Aext, long long aOff,
    const float* __restrict__ Bw, const float* __restrict__ bias,
    int useRowscale, float biasScale, long long cOff,
    int M, int N, int K, int lda, int ldb, int ldc,
    long long aStride, long long cStride, int relu)
{
    const float* A = (Aext ? Aext : (const float*)g_buf) + aOff
                     + (long long)blockIdx.z * aStride;
    float* C = g_buf + cOff + (long long)blockIdx.z * cStride;

    int tidx = threadIdx.x;
    int tx = tidx & 15;
    int ty = tidx >> 4;
    int m0 = blockIdx.y * GBM;
    int n0 = blockIdx.x * GBN;

    __shared__ float As[GBK][GBM];
    __shared__ float Bs[GBK][GBN];

    float acc[8][4];
#pragma unroll
    for (int i = 0; i < 8; i++)
#pragma unroll
        for (int j = 0; j < 4; j++) acc[i][j] = 0.0f;

    for (int k0 = 0; k0 < K; k0 += GBK) {
#pragma unroll
        for (int l = 0; l < 2; l++) {
            int idx = tidx * 2 + l;
            int r = idx >> 2;
            int kq = (idx & 3) * 4;
            float4 v = make_float4(0.f, 0.f, 0.f, 0.f);
            int m = m0 + r;
            if (m < M) v = *(const float4*)(A + (long long)m * lda + k0 + kq);
            As[kq + 0][r] = v.x; As[kq + 1][r] = v.y;
            As[kq + 2][r] = v.z; As[kq + 3][r] = v.w;
        }
        {
            int r = tidx >> 4;
            int c = (tidx & 15) * 4;
            *(float4*)&Bs[r][c] = *(const float4*)(Bw + (long long)(k0 + r) * ldb + n0 + c);
        }
        __syncthreads();
#pragma unroll
        for (int kk = 0; kk < GBK; kk++) {
            float4 a0 = *(const float4*)&As[kk][ty * 8];
            float4 a1 = *(const float4*)&As[kk][ty * 8 + 4];
            float4 b0 = *(const float4*)&Bs[kk][tx * 4];
            float a[8] = {a0.x, a0.y, a0.z, a0.w, a1.x, a1.y, a1.z, a1.w};
            float br[4] = {b0.x, b0.y, b0.z, b0.w};
#pragma unroll
            for (int i = 0; i < 8; i++)
#pragma unroll
                for (int j = 0; j < 4; j++) acc[i][j] = fmaf(a[i], br[j], acc[i][j]);
        }
        __syncthreads();
    }

    const float* rowscale = useRowscale ? (const float*)g_buf + OFF_RS : nullptr;
#pragma unroll
    for (int i = 0; i < 8; i++) {
        int m = m0 + ty * 8 + i;
        if (m >= M) continue;
        float rs = biasScale * (rowscale ? rowscale[m] : 1.0f);
#pragma unroll
        for (int j = 0; j < 4; j++) {
            int nn = n0 + tx * 4 + j;
            float v = acc[i][j];
            if (bias) v += rs * bias[nn];
            if (relu) v = fmaxf(v, 0.0f);
            C[(long long)m * ldc + nn] = v;
        }
    }
}

// ---------------------------------------------------------------------------
// Reductions / glue
// ---------------------------------------------------------------------------
__global__ void reduce_kernel() {
    int b = blockIdx.y;
    int x = blockIdx.x;
    int f = threadIdx.x;
    const float* Yb = g_buf + OFF_Y + (long long)b * NTOT * HID;

    if (x < KC) {
        int s = g_starts[x], c = g_counts[x];
        float a0 = 0.f, a1 = 0.f, a2 = 0.f, a3 = 0.f;
        int i = 0;
        for (; i + 4 <= c; i += 4) {
            a0 += Yb[(long long)g_order[s + i + 0] * HID + f];
            a1 += Yb[(long long)g_order[s + i + 1] * HID + f];
            a2 += Yb[(long long)g_order[s + i + 2] * HID + f];
            a3 += Yb[(long long)g_order[s + i + 3] * HID + f];
        }
        for (; i < c; i++) a0 += Yb[(long long)g_order[s + i] * HID + f];
        g_buf[OFF_RH + ((long long)b * (KC + 1) + x) * HID + f] = (a0 + a1) + (a2 + a3);
    } else if (x == KC) {
        g_buf[OFF_RH + ((long long)b * (KC + 1) + KC) * HID + f] =
            Yb[(long long)NTOK * HID + f];
    } else {
        int c = x - KC - 1;
        int t0 = NH + c * 256;
        int t1 = min(NTOT, t0 + 256);
        float a0 = 0.f, a1 = 0.f, a2 = 0.f, a3 = 0.f;
        int t = t0;
        for (; t + 4 <= t1; t += 4) {
            a0 += Yb[(long long)(t + 0) * HID + f];
            a1 += Yb[(long long)(t + 1) * HID + f];
            a2 += Yb[(long long)(t + 2) * HID + f];
            a3 += Yb[(long long)(t + 3) * HID + f];
        }
        for (; t < t1; t++) a0 += Yb[(long long)t * HID + f];
        g_buf[OFF_RQP + ((long long)c * BB + b) * HID + f] = (a0 + a1) + (a2 + a3);
    }
}

__global__ void reduce_q_kernel() {
    int b = blockIdx.x, f = threadIdx.x;
    float acc = 0.f;
#pragma unroll
    for (int c = 0; c < QCHUNK; c++)
        acc += g_buf[OFF_RQP + ((long long)c * BB + b) * HID + f];
    g_buf[OFF_RQ + (long long)b * HID + f] = acc;
}

__global__ void build_H_kernel() {
    int row = blockIdx.x;
    int b = row / (2 * KC + 1), j = row % (2 * KC + 1);
    int f = threadIdx.x;
    const float* Hk = g_buf + OFF_HK + (long long)b * (KC + 1) * HDIM;
    float hn = Hk[KC * HDIM + f];
    float v = (j < KC) ? Hk[j * HDIM + f]
            : (j < 2 * KC) ? Hk[(j - KC) * HDIM + f] + hn
            : hn;
    g_buf[OFF_H + (long long)row * HDIM + f] = v;
}

__global__ void compute_S_kernel() {
    int b = blockIdx.x, f = threadIdx.x;
    const float* gsb = g_buf + OFF_GS + (long long)b * (2 * KC + 1) * GDIM;
    float acc = 0.f;
#pragma unroll
    for (int k = 0; k < KC; k++) acc += gsb[(long long)k * GDIM + f];
    g_buf[OFF_S + (long long)b * GDIM + f] = acc;
}

__global__ void build_uu_kernel() {
    int row = blockIdx.x;
    int b = row / (KC + 1), j = row % (KC + 1);
    int f = threadIdx.x;
    float v;
    if (f < GDIM) {
        float S = g_buf[OFF_S + (long long)b * GDIM + f];
        const float* gsb = g_buf + OFF_GS + (long long)b * (2 * KC + 1) * GDIM;
        if (j < KC) v = S - gsb[(long long)j * GDIM + f] + gsb[(long long)(KC + j) * GDIM + f];
        else        v = S + gsb[(long long)(2 * KC) * GDIM + f];
    } else {
        v = g_buf[OFF_Q + (long long)b * HDIM + (f - GDIM)];
    }
    g_buf[OFF_UU + (long long)row * (GDIM + HDIM) + f] = v;
}

__global__ void final_kernel(const float* __restrict__ We2, float* __restrict__ out) {
    int w = (blockIdx.x * blockDim.x + threadIdx.x) >> 5;
    int lane = threadIdx.x & 31;
    if (w >= ROWS_E) return;
    const float* r = g_buf + OFF_EH + (long long)w * HID;
    float acc = 0.f;
    for (int i = lane; i < HID; i += 32) acc += r[i] * We2[i];
#pragma unroll
    for (int o = 16; o; o >>= 1) acc += __shfl_xor_sync(0xffffffffu, acc, o);
    if (lane == 0) {
        out[w] = acc;
        out[ROWS_E + w] = 1.0f;
    }
}

// ---------------------------------------------------------------------------
// Launch
// ---------------------------------------------------------------------------
static inline void launch_sgemm(const float* Aext, long long aOff,
                                const float* Bw, const float* bias,
                                int useRS, float biasScale, long long cOff,
                                int M, int N, int K, int lda, int ldb, int ldc,
                                long long aStride, long long cStride, int Z, int relu)
{
    dim3 grid(N / GBN, (M + GBM - 1) / GBM, Z);
    sgemm_kernel<<<grid, 256>>>(Aext, aOff, Bw, bias, useRS, biasScale, cOff,
                                M, N, K, lda, ldb, ldc, aStride, cStride, relu);
}

extern "C" void kernel_launch(void* const* d_in, const int* in_sizes, int n_in,
                              void* d_out, int out_size) {
    const float* data = (const float*)d_in[0];
    const int*   cs   = (const int*)  d_in[1];
    const float* Wh1 = (const float*)d_in[3];
    const float* bh1 = (const float*)d_in[4];
    const float* Wh2 = (const float*)d_in[5];
    const float* bh2 = (const float*)d_in[6];
    const float* Wq1 = (const float*)d_in[7];
    const float* bq1 = (const float*)d_in[8];
    const float* Wq2 = (const float*)d_in[9];
    const float* bq2 = (const float*)d_in[10];
    const float* Wg1 = (const float*)d_in[11];
    const float* bg1 = (const float*)d_in[12];
    const float* Wg2 = (const float*)d_in[13];
    const float* bg2 = (const float*)d_in[14];
    const float* We1 = (const float*)d_in[15];
    const float* be1 = (const float*)d_in[16];
    const float* We2 = (const float*)d_in[17];
    float* out = (float*)d_out;

    // 1) cluster counting-sort + bias row scales + weight transpose
    build_order_kernel<<<1, 1024>>>(cs);
    build_rowscale_kernel<<<(ROWS_HK + 255) / 256, 256>>>();
    prep_weights_kernel<<<(XD * HID + 255) / 256, 256>>>(Wh1, Wq1);

    // 2) layer-1 wmma TF32 tensor cores, cp.async double-buffered -> Y
    cudaFuncSetAttribute(layer1_wmma_kernel,
                         cudaFuncAttributeMaxDynamicSharedMemorySize, L1_SMEM);
    layer1_wmma_kernel<<<dim3(4, 33, BB), 512, L1_SMEM>>>(data, bh1, bq1);

    // 3) deterministic cluster / Q reductions over Y
    reduce_kernel<<<dim3(KC + 1 + QCHUNK, BB), 512>>>();
    reduce_q_kernel<<<BB, 512>>>();

    // 4) Hk = Rh @ Wh2 + counts*bh2
    launch_sgemm(nullptr, OFF_RH, Wh2, bh2, 1, 1.0f, OFF_HK,
                 ROWS_HK, HDIM, HID, HID, HDIM, HDIM, 0, 0, 1, 0);
    // 5) Q = Rq @ Wq2 + 2047*bq2
    launch_sgemm(nullptr, OFF_RQ, Wq2, bq2, 0, (float)NQ, OFF_Q,
                 BB, HDIM, HID, HID, HDIM, HDIM, 0, 0, 1, 0);

    // 6) g-MLP on H
    build_H_kernel<<<ROWS_H, HDIM>>>();
    launch_sgemm(nullptr, OFF_H, Wg1, bg1, 0, 1.0f, OFF_G1,
                 ROWS_H, HID, HDIM, HDIM, HID, HID, 0, 0, 1, 1);
    launch_sgemm(nullptr, OFF_G1, Wg2, bg2, 0, 1.0f, OFF_GS,
                 ROWS_H, GDIM, HID, HID, GDIM, GDIM, 0, 0, 1, 0);

    // 7) combine G + Q -> uu, then energy MLP
    compute_S_kernel<<<BB, GDIM>>>();
    build_uu_kernel<<<ROWS_E, GDIM + HDIM>>>();
    launch_sgemm(nullptr, OFF_UU, We1, be1, 0, 1.0f, OFF_EH,
                 ROWS_E, HID, GDIM + HDIM, GDIM + HDIM, HID, HID, 0, 0, 1, 1);
    final_kernel<<<(ROWS_E * 32 + 255) / 256, 256>>>(We2, out);
}